// round 15
// baseline (speedup 1.0000x reference)
#include <cuda_runtime.h>
#include <cuda_fp16.h>
#include <math.h>
#include <stdint.h>

#define B_N 8192
#define K_N 4096
#define D_N 512
#define NCAND 64           // 2 per 128-node block
#define NSEL 8             // global top-8 rescored exactly

static constexpr float LR     = 0.3f;
static constexpr float AT     = 0.9f;
static constexpr float DSBETA = 1e-4f;
static constexpr float EPS_DS = 0.01f;

// ---------------- scratch (device globals) ----------------
__device__ signed char g_x8[B_N * D_N];
__device__ signed char g_w8[K_N * D_N];
__device__ float g_xs[B_N];          // per-row x quant scale
__device__ float g_ws[K_N];          // per-node w quant scale
__device__ float g_xsq[B_N];
__device__ float g_wsq[K_N];
__device__ float g_relsum[K_N];
__device__ int   g_cand_idx[B_N * NCAND];
__device__ float g_cand_val[B_N * NCAND];
__device__ float g_cnt[K_N];
__device__ float g_cntl[K_N];
__device__ float g_sums[K_N * D_N];
__device__ float g_sumsl[K_N * D_N];
__device__ float g_nc1[K_N];
__device__ int   g_lowvalid[K_N];
__device__ int   g_availrank[K_N];
__device__ int   g_validids[K_N];
__device__ float g_loss;
__device__ int   g_nnew;
__device__ int   g_ncreate;

// ---------------- helpers ----------------
__device__ __forceinline__ uint32_t smem_u32(const void* p) {
    uint32_t a;
    asm("{ .reg .u64 t; cvta.to.shared.u64 t, %1; cvt.u32.u64 %0, t; }" : "=r"(a) : "l"(p));
    return a;
}
#define SW64(o) ((o) ^ (((o) >> 3) & 0x30))
#define BETTER(v, k, bv, bk) ((v) > (bv) || ((v) == (bv) && (k) < (bk)))

__device__ __forceinline__ void ldsm_x4(uint32_t (&r)[4], uint32_t addr) {
    asm volatile("ldmatrix.sync.aligned.m8n8.x4.shared.b16 {%0,%1,%2,%3}, [%4];"
                 : "=r"(r[0]), "=r"(r[1]), "=r"(r[2]), "=r"(r[3]) : "r"(addr));
}
// int8 IMMA: D(s32) = A(s8)[16x32] * B(s8)[8x32]^T + D
__device__ __forceinline__ void mma16832(int (&d)[4], const uint32_t (&a)[4], const uint32_t* b) {
    asm volatile("mma.sync.aligned.m16n8k32.row.col.s32.s8.s8.s32 "
                 "{%0,%1,%2,%3}, {%4,%5,%6,%7}, {%8,%9}, {%0,%1,%2,%3};"
                 : "+r"(d[0]), "+r"(d[1]), "+r"(d[2]), "+r"(d[3])
                 : "r"(a[0]), "r"(a[1]), "r"(a[2]), "r"(a[3]), "r"(b[0]), "r"(b[1]));
}
__device__ __forceinline__ int q8(float v, float inv) {
    float r = rintf(v * inv);
    r = fminf(fmaxf(r, -127.f), 127.f);
    return (int)r;
}

struct Top2 {
    float v1, v2;
    int   k1, k2;
    __device__ __forceinline__ void init() { v1 = v2 = -1e30f; k1 = k2 = 0x7fffffff; }
    __device__ __forceinline__ void insert(float v, int k) {
        if (BETTER(v, k, v1, k1)) { v2 = v1; k2 = k1; v1 = v; k1 = k; }
        else if (BETTER(v, k, v2, k2)) { v2 = v; k2 = k; }
    }
    __device__ __forceinline__ void merge(float o1, int ok1, float o2, int ok2) {
        if (BETTER(o1, ok1, v1, k1)) {
            if (BETTER(v1, k1, o2, ok2)) { v2 = v1; k2 = k1; }
            else                         { v2 = o2; k2 = ok2; }
            v1 = o1; k1 = ok1;
        } else if (BETTER(o1, ok1, v2, k2)) {
            v2 = o1; k2 = ok1;
        }
    }
};

// ---------------- Kernel S: fused int8-quantize + row stats (warp per row) ----------------
__global__ void split_stats_kernel(const float* __restrict__ X, const float* __restrict__ W,
                                   const float* __restrict__ R) {
    int row  = (blockIdx.x * blockDim.x + threadIdx.x) >> 5;
    int lane = threadIdx.x & 31;
    if (row < B_N) {
        const float4* xr = (const float4*)(X + (size_t)row * D_N);
        float4 v[4];
        float s = 0.f, mx = 0.f;
#pragma unroll
        for (int i = 0; i < 4; ++i) {
            v[i] = xr[lane + i * 32];
            s += v[i].x * v[i].x + v[i].y * v[i].y + v[i].z * v[i].z + v[i].w * v[i].w;
            mx = fmaxf(mx, fmaxf(fmaxf(fabsf(v[i].x), fabsf(v[i].y)),
                                 fmaxf(fabsf(v[i].z), fabsf(v[i].w))));
        }
#pragma unroll
        for (int o = 16; o; o >>= 1) {
            s  += __shfl_xor_sync(0xFFFFFFFFu, s, o);
            mx  = fmaxf(mx, __shfl_xor_sync(0xFFFFFFFFu, mx, o));
        }
        float scale = fmaxf(mx, 1e-30f) / 127.f;
        float inv   = 1.f / scale;
#pragma unroll
        for (int i = 0; i < 4; ++i) {
            int d4 = lane + i * 32;
            uint32_t packed = (uint32_t)(q8(v[i].x, inv) & 0xFF)
                            | ((uint32_t)(q8(v[i].y, inv) & 0xFF) << 8)
                            | ((uint32_t)(q8(v[i].z, inv) & 0xFF) << 16)
                            | ((uint32_t)(q8(v[i].w, inv) & 0xFF) << 24);
            *(uint32_t*)&g_x8[(size_t)row * D_N + d4 * 4] = packed;
        }
        if (lane == 0) { g_xsq[row] = s; g_xs[row] = scale; }
    } else {
        int k = row - B_N;
        if (k >= K_N) return;
        const float4* wr = (const float4*)(W + (size_t)k * D_N);
        const float4* rr = (const float4*)(R + (size_t)k * D_N);
        float4 v[4];
        float s1 = 0.f, s2 = 0.f, mx = 0.f;
#pragma unroll
        for (int i = 0; i < 4; ++i) {
            v[i] = wr[lane + i * 32];
            float4 u = rr[lane + i * 32];
            s1 += v[i].x * v[i].x + v[i].y * v[i].y + v[i].z * v[i].z + v[i].w * v[i].w;
            s2 += u.x + u.y + u.z + u.w;
            mx = fmaxf(mx, fmaxf(fmaxf(fabsf(v[i].x), fabsf(v[i].y)),
                                 fmaxf(fabsf(v[i].z), fabsf(v[i].w))));
        }
#pragma unroll
        for (int o = 16; o; o >>= 1) {
            s1 += __shfl_xor_sync(0xFFFFFFFFu, s1, o);
            s2 += __shfl_xor_sync(0xFFFFFFFFu, s2, o);
            mx  = fmaxf(mx, __shfl_xor_sync(0xFFFFFFFFu, mx, o));
        }
        float scale = fmaxf(mx, 1e-30f) / 127.f;
        float inv   = 1.f / scale;
#pragma unroll
        for (int i = 0; i < 4; ++i) {
            int d4 = lane + i * 32;
            uint32_t packed = (uint32_t)(q8(v[i].x, inv) & 0xFF)
                            | ((uint32_t)(q8(v[i].y, inv) & 0xFF) << 8)
                            | ((uint32_t)(q8(v[i].z, inv) & 0xFF) << 16)
                            | ((uint32_t)(q8(v[i].w, inv) & 0xFF) << 24);
            *(uint32_t*)&g_w8[(size_t)k * D_N + d4 * 4] = packed;
        }
        if (lane == 0) { g_wsq[k] = s1; g_relsum[k] = s2; g_ws[k] = scale; }
    }
}

// ---------------- Kernel B: int8 IMMA GEMM screen -> per-block top-2 ----------------
// 512 threads, 4x4 warp grid, warp tile 32x32. KC=64 int8 (64B rows, SW64).
// Stage = A 8KB + B 8KB = 16KB, 3 stages, 8 chunks, 2 kk-steps (k32) per chunk.
#define KC 64
#define STAGE_BYTES 16384
#define OFF_A 0
#define OFF_B 8192
#define NSTAGE 3
#define NCHUNK (D_N / KC)                        // 8
#define SM_STATS (NSTAGE * STAGE_BYTES)          // 49152
#define SMEM_TOTAL (SM_STATS + 1536 + 8192)      // stats(3x512) + rb/rk
#define NTHR 512

__device__ __forceinline__ void load_tile_async(uint32_t sdst, const signed char* __restrict__ g,
                                                int grow0, int dt, int tid) {
    // 128 rows x 64B = 512 x 16B units; 512 threads -> 1 unit each
    int row = tid >> 2, c = tid & 3;
    const signed char* src = g + (size_t)(grow0 + row) * D_N + dt + c * 16;
    uint32_t dst = sdst + SW64(row * 64 + c * 16);
    asm volatile("cp.async.cg.shared.global [%0], [%1], 16;" :: "r"(dst), "l"(src));
}

__global__ __launch_bounds__(NTHR, 2) void gemm_mma_kernel() {
    extern __shared__ char smem[];
    uint32_t sb = smem_u32(smem);
    int tid  = threadIdx.x;
    int lane = tid & 31;
    int warp = tid >> 5;          // 0..15
    int wm = warp >> 2, wn = warp & 3;   // 4 x 4
    int row0 = blockIdx.y * 128;
    int n0   = blockIdx.x * 128;

    float* swsq = (float*)(smem + SM_STATS);
    float* srs  = (float*)(smem + SM_STATS + 512);
    float* sws  = (float*)(smem + SM_STATS + 1024);
    float* rb1  = (float*)(smem + SM_STATS + 1536);
    int*   rk1  = (int*)  (smem + SM_STATS + 3584);
    float* rb2  = (float*)(smem + SM_STATS + 5632);
    int*   rk2  = (int*)  (smem + SM_STATS + 7680);
    if (tid < 128) {
        swsq[tid] = g_wsq[n0 + tid];
        srs[tid]  = g_relsum[n0 + tid];
        sws[tid]  = g_ws[n0 + tid];
    }

    {
        load_tile_async(sb + OFF_A, g_x8, row0, 0, tid);
        load_tile_async(sb + OFF_B, g_w8, n0, 0, tid);
        asm volatile("cp.async.commit_group;" ::: "memory");
        uint32_t st1 = sb + STAGE_BYTES;
        load_tile_async(st1 + OFF_A, g_x8, row0, KC, tid);
        load_tile_async(st1 + OFF_B, g_w8, n0, KC, tid);
        asm volatile("cp.async.commit_group;" ::: "memory");
    }

    int acc[2][4][4];
#pragma unroll
    for (int mi = 0; mi < 2; ++mi)
#pragma unroll
        for (int ni = 0; ni < 4; ++ni)
#pragma unroll
            for (int j = 0; j < 4; ++j) acc[mi][ni][j] = 0;

    int aRow = lane & 15, aK = lane >> 4;                  // aK: 16B chunk within 32B kstep
    int bRowP = 8 * ((lane >> 4) & 1) + (lane & 7);
    int bK    = (lane >> 3) & 1;

    for (int c = 0; c < NCHUNK; ++c) {
        if (c < NCHUNK - 1) asm volatile("cp.async.wait_group 1;" ::: "memory");
        else                asm volatile("cp.async.wait_group 0;" ::: "memory");
        __syncthreads();

        if (c + 2 < NCHUNK) {
            uint32_t pst = sb + ((c + 2) % 3) * STAGE_BYTES;
            int dt = (c + 2) * KC;
            load_tile_async(pst + OFF_A, g_x8, row0, dt, tid);
            load_tile_async(pst + OFF_B, g_w8, n0, dt, tid);
            asm volatile("cp.async.commit_group;" ::: "memory");
        }

        uint32_t st = sb + (c % 3) * STAGE_BYTES;
#pragma unroll
        for (int kk = 0; kk < 2; ++kk) {       // two k32 steps per 64B chunk
            uint32_t ah[2][4];
#pragma unroll
            for (int mi = 0; mi < 2; ++mi) {
                uint32_t off = SW64((32 * wm + 16 * mi + aRow) * 64 + kk * 32 + aK * 16);
                ldsm_x4(ah[mi], st + OFF_A + off);
            }
            uint32_t bh[2][4];
#pragma unroll
            for (int nj = 0; nj < 2; ++nj) {
                uint32_t off = SW64((32 * wn + 16 * nj + bRowP) * 64 + kk * 32 + bK * 16);
                ldsm_x4(bh[nj], st + OFF_B + off);
            }
#pragma unroll
            for (int mi = 0; mi < 2; ++mi)
#pragma unroll
                for (int ni = 0; ni < 4; ++ni) {
                    const uint32_t* pbh = &bh[ni >> 1][(ni & 1) * 2];
                    mma16832(acc[mi][ni], ah[mi], pbh);
                }
        }
    }

    // ---------------- epilogue: dequant + act + per-row per-block top-2 ----------------
    const float invD = 1.0f / (float)D_N;
    int t4 = lane >> 2;
#pragma unroll
    for (int mi = 0; mi < 2; ++mi) {
        int r0l = 32 * wm + 16 * mi + t4;
        float xsq0 = g_xsq[row0 + r0l];
        float xsq1 = g_xsq[row0 + r0l + 8];
        float xs0  = g_xs[row0 + r0l];
        float xs1  = g_xs[row0 + r0l + 8];
        Top2 tA, tB;
        tA.init(); tB.init();
#pragma unroll
        for (int ni = 0; ni < 4; ++ni) {
#pragma unroll
            for (int j = 0; j < 2; ++j) {
                int nl = 32 * wn + 8 * ni + 2 * (lane & 3) + j;
                int kg = n0 + nl;
                float wsq = swsq[nl], rs = srs[nl], sw = sws[nl];
                float rsd = rs * invD;
                float dot0 = (float)acc[mi][ni][j] * (xs0 * sw);
                float d0  = xsq0 + wsq - 2.f * dot0;
                float a0v = rs / (rs + d0 * rsd + 1e-7f);
                tA.insert(a0v, kg);
                float dot1 = (float)acc[mi][ni][2 + j] * (xs1 * sw);
                float d1  = xsq1 + wsq - 2.f * dot1;
                float a1v = rs / (rs + d1 * rsd + 1e-7f);
                tB.insert(a1v, kg);
            }
        }
#pragma unroll
        for (int o = 1; o <= 2; o <<= 1) {
            float o1 = __shfl_xor_sync(0xFFFFFFFFu, tA.v1, o);
            int  ok1 = __shfl_xor_sync(0xFFFFFFFFu, tA.k1, o);
            float o2 = __shfl_xor_sync(0xFFFFFFFFu, tA.v2, o);
            int  ok2 = __shfl_xor_sync(0xFFFFFFFFu, tA.k2, o);
            tA.merge(o1, ok1, o2, ok2);
            o1 = __shfl_xor_sync(0xFFFFFFFFu, tB.v1, o);
            ok1 = __shfl_xor_sync(0xFFFFFFFFu, tB.k1, o);
            o2 = __shfl_xor_sync(0xFFFFFFFFu, tB.v2, o);
            ok2 = __shfl_xor_sync(0xFFFFFFFFu, tB.k2, o);
            tB.merge(o1, ok1, o2, ok2);
        }
        if ((lane & 3) == 0) {
            rb1[r0l * 4 + wn] = tA.v1;  rk1[r0l * 4 + wn] = tA.k1;
            rb2[r0l * 4 + wn] = tA.v2;  rk2[r0l * 4 + wn] = tA.k2;
            rb1[(r0l + 8) * 4 + wn] = tB.v1;  rk1[(r0l + 8) * 4 + wn] = tB.k1;
            rb2[(r0l + 8) * 4 + wn] = tB.v2;  rk2[(r0l + 8) * 4 + wn] = tB.k2;
        }
    }
    __syncthreads();
    if (tid < 128) {
        Top2 t;
        t.v1 = rb1[tid * 4]; t.k1 = rk1[tid * 4];
        t.v2 = rb2[tid * 4]; t.k2 = rk2[tid * 4];
#pragma unroll
        for (int j = 1; j < 4; ++j)
            t.merge(rb1[tid * 4 + j], rk1[tid * 4 + j], rb2[tid * 4 + j], rk2[tid * 4 + j]);
        size_t base = (size_t)(row0 + tid) * NCAND + blockIdx.x * 2;
        g_cand_idx[base]     = t.k1;  g_cand_val[base]     = t.v1;
        g_cand_idx[base + 1] = t.k2;  g_cand_val[base + 1] = t.v2;
    }
}

// ---------------- Kernel R: fused merge(top-8) + exact fp32 rescore + scatter ----------------
__global__ __launch_bounds__(256) void rescore_scatter_kernel(const float* __restrict__ X,
                                                              const float* __restrict__ W) {
    int warp = threadIdx.x >> 5, lane = threadIdx.x & 31;
    int b = blockIdx.x * 8 + warp;
    size_t cbase = (size_t)b * NCAND;
    float v0 = g_cand_val[cbase + lane],  v1 = g_cand_val[cbase + 32 + lane];
    int   k0 = g_cand_idx[cbase + lane],  k1 = g_cand_idx[cbase + 32 + lane];

    int sel[NSEL];
#pragma unroll
    for (int r = 0; r < NSEL; ++r) {
        float bv; int bk;
        if (BETTER(v0, k0, v1, k1)) { bv = v0; bk = k0; } else { bv = v1; bk = k1; }
#pragma unroll
        for (int o = 16; o; o >>= 1) {
            float ov = __shfl_xor_sync(0xFFFFFFFFu, bv, o);
            int   ok = __shfl_xor_sync(0xFFFFFFFFu, bk, o);
            if (BETTER(ov, ok, bv, bk)) { bv = ov; bk = ok; }
        }
        sel[r] = bk;
        if (v0 == bv && k0 == bk) { v0 = -1e30f; k0 = 0x7fffffff; }
        else if (v1 == bv && k1 == bk) { v1 = -1e30f; k1 = 0x7fffffff; }
    }

    const float4* xr = (const float4*)(X + (size_t)b * D_N);
    float4 xv[4];
#pragma unroll
    for (int i = 0; i < 4; ++i) xv[i] = xr[lane + i * 32];

    float xsq = g_xsq[b];
    const float invD = 1.0f / (float)D_N;

    float bv = -1e30f;
    int   bk = 0x7fffffff;
#pragma unroll
    for (int r = 0; r < NSEL; ++r) {
        int k = sel[r];
        const float4* wr = (const float4*)(W + (size_t)k * D_N);
        float acc = 0.f;
#pragma unroll
        for (int i = 0; i < 4; ++i) {
            float4 wv = wr[lane + i * 32];
            acc = fmaf(xv[i].x, wv.x, acc); acc = fmaf(xv[i].y, wv.y, acc);
            acc = fmaf(xv[i].z, wv.z, acc); acc = fmaf(xv[i].w, wv.w, acc);
        }
#pragma unroll
        for (int o = 16; o; o >>= 1) acc += __shfl_xor_sync(0xFFFFFFFFu, acc, o);

        float wsq = g_wsq[k], rs = g_relsum[k];
        float rsd  = rs * invD;
        float dist = xsq + wsq - 2.f * acc;
        float act  = rs / (rs + dist * rsd + 1e-7f);
        if (BETTER(act, k, bv, bk)) { bv = act; bk = k; }
    }

    int high = (bv >= AT) ? 1 : 0;
    float* sums = high ? g_sums : g_sumsl;
    float* cnt  = high ? g_cnt  : g_cntl;
    if (lane == 0) atomicAdd(&cnt[bk], 1.0f);
    float* dst = sums + (size_t)bk * D_N;
#pragma unroll
    for (int i = 0; i < 4; ++i) {
        int d = (lane + i * 32) * 4;
        atomicAdd(&dst[d + 0], xv[i].x);
        atomicAdd(&dst[d + 1], xv[i].y);
        atomicAdd(&dst[d + 2], xv[i].z);
        atomicAdd(&dst[d + 3], xv[i].w);
    }
}

// ---------------- Kernel D: per-node high-branch update ----------------
__global__ __launch_bounds__(256) void update_kernel(
    const float* __restrict__ W, const float* __restrict__ MA,
    const float* __restrict__ REL, const float* __restrict__ NC,
    float* __restrict__ out)
{
    int k = blockIdx.x;
    int t = threadIdx.x;

    float cntk = g_cnt[k];
    int   upd  = cntk > 0.f;
    float inv  = upd ? 1.f / cntk : 1.f;

    float* outw   = out + 1;
    float* outma  = out + 1 + (size_t)K_N * D_N;
    float* outrel = out + 1 + 2 * (size_t)K_N * D_N;
    float* outnc  = out + 1 + 3 * (size_t)K_N * D_N;

    const float a = LR * DSBETA;

    float wv[2], meanv[2], ma1v[2];
    float mx = -1e30f, mn = 1e30f, sm = 0.f, lsum = 0.f;
#pragma unroll
    for (int e = 0; e < 2; e++) {
        int d = t + e * 256;
        size_t off = (size_t)k * D_N + d;
        float w  = W[off];
        float m  = upd ? g_sums[off] * inv : 0.f;
        float ma = MA[off];
        float m1 = upd ? (a * fabsf(m - w) + (1.f - a) * ma) : ma;
        wv[e] = w; meanv[e] = m; ma1v[e] = m1;
        mx = fmaxf(mx, m1); mn = fminf(mn, m1); sm += m1;
        if (upd) lsum += LR * (m - w);
    }

    __shared__ float smax[8], smin[8], ssum[8], sls[8];
#pragma unroll
    for (int o = 16; o; o >>= 1) {
        mx   = fmaxf(mx, __shfl_xor_sync(0xFFFFFFFFu, mx, o));
        mn   = fminf(mn, __shfl_xor_sync(0xFFFFFFFFu, mn, o));
        sm  += __shfl_xor_sync(0xFFFFFFFFu, sm, o);
        lsum += __shfl_xor_sync(0xFFFFFFFFu, lsum, o);
    }
    int wrp = t >> 5, lane = t & 31;
    if (lane == 0) { smax[wrp] = mx; smin[wrp] = mn; ssum[wrp] = sm; sls[wrp] = lsum; }
    __syncthreads();
    mx = smax[0]; mn = smin[0]; sm = 0.f; float ltot = 0.f;
#pragma unroll
    for (int wgi = 0; wgi < 8; wgi++) {
        mx = fmaxf(mx, smax[wgi]); mn = fminf(mn, smin[wgi]);
        sm += ssum[wgi]; ltot += sls[wgi];
    }

    float av     = sm * (1.f / (float)D_N);
    float idenom = 1.f / (EPS_DS * (mx - mn));

#pragma unroll
    for (int e = 0; e < 2; e++) {
        int d = t + e * 256;
        size_t off = (size_t)k * D_N + d;
        float m1  = ma1v[e];
        float rel = upd ? 1.f / (1.f + expf((m1 - av) * idenom)) : REL[off];
        float w1  = upd ? wv[e] + LR * (meanv[e] - wv[e]) : wv[e];
        outw[off]  = w1;
        outma[off] = m1;
        outrel[off] = rel;
    }
    if (t == 0) {
        float nc1 = upd ? 1.f : NC[k];
        g_nc1[k] = nc1;
        outnc[k] = nc1;
        g_lowvalid[k] = (g_cntl[k] > 0.f) ? 1 : 0;
        if (upd) atomicAdd(&g_loss, ltot);
    }
}

// ---------------- Kernel E: single-block scan for add_node ----------------
__global__ void scan_kernel(float* __restrict__ out) {
    __shared__ int s_lv[1024];
    __shared__ int s_av[1024];
    int t = threadIdx.x;
    int lvloc[4], avloc[4];
    int lv = 0, av = 0;
#pragma unroll
    for (int j = 0; j < 4; j++) {
        int k = t * 4 + j;
        int l  = g_lowvalid[k];
        int a2 = (g_nc1[k] == 0.f) ? 1 : 0;
        lvloc[j] = l; avloc[j] = a2;
        lv += l; av += a2;
    }
    s_lv[t] = lv; s_av[t] = av;
    __syncthreads();
    for (int o = 1; o < 1024; o <<= 1) {
        int a = 0, b2 = 0;
        if (t >= o) { a = s_lv[t - o]; b2 = s_av[t - o]; }
        __syncthreads();
        if (t >= o) { s_lv[t] += a; s_av[t] += b2; }
        __syncthreads();
    }
    int nnew   = s_lv[1023];
    int navail = s_av[1023];
    int exlv = s_lv[t] - lv;
    int exav = s_av[t] - av;
#pragma unroll
    for (int j = 0; j < 4; j++) {
        int k = t * 4 + j;
        if (lvloc[j]) { g_validids[exlv] = k; exlv++; }
        if (avloc[j]) { g_availrank[k] = exav; exav++; }
    }
    if (t == 0) {
        g_nnew = nnew;
        g_ncreate = nnew < navail ? nnew : navail;
        out[0] = g_loss / (float)B_N;
    }
}

// ---------------- Kernel F: add_node slot fill ----------------
__global__ void addnode_kernel(float* __restrict__ out) {
    int k = blockIdx.x;
    if (g_nc1[k] != 0.f) return;
    int r = g_availrank[k];
    int ncreate = g_ncreate;
    if (r >= ncreate) return;
    int src = g_validids[g_nnew - ncreate + r];
    float inv = 1.f / g_cntl[src];

    float* outw   = out + 1;
    float* outma  = out + 1 + (size_t)K_N * D_N;
    float* outrel = out + 1 + 2 * (size_t)K_N * D_N;
    float* outnc  = out + 1 + 3 * (size_t)K_N * D_N;

    for (int d = threadIdx.x; d < D_N; d += blockDim.x) {
        size_t off = (size_t)k * D_N + d;
        outw[off]   = g_sumsl[(size_t)src * D_N + d] * inv;
        outma[off]  = 0.f;
        outrel[off] = 1.f;
    }
    if (threadIdx.x == 0) outnc[k] = 1.f;
}

// ---------------- launch ----------------
extern "C" void kernel_launch(void* const* d_in, const int* in_sizes, int n_in,
                              void* d_out, int out_size) {
    const float* X   = (const float*)d_in[0];
    const float* W   = (const float*)d_in[1];
    const float* MA  = (const float*)d_in[2];
    const float* REL = (const float*)d_in[3];
    const float* NC  = (const float*)d_in[4];
    float* out = (float*)d_out;

    void* p;
    cudaGetSymbolAddress(&p, g_cnt);   cudaMemsetAsync(p, 0, K_N * sizeof(float));
    cudaGetSymbolAddress(&p, g_cntl);  cudaMemsetAsync(p, 0, K_N * sizeof(float));
    cudaGetSymbolAddress(&p, g_sums);  cudaMemsetAsync(p, 0, (size_t)K_N * D_N * sizeof(float));
    cudaGetSymbolAddress(&p, g_sumsl); cudaMemsetAsync(p, 0, (size_t)K_N * D_N * sizeof(float));
    cudaGetSymbolAddress(&p, g_loss);  cudaMemsetAsync(p, 0, sizeof(float));

    split_stats_kernel<<<(B_N + K_N) / 8, 256>>>(X, W, REL);

    cudaFuncSetAttribute(gemm_mma_kernel, cudaFuncAttributeMaxDynamicSharedMemorySize, SMEM_TOTAL);
    dim3 grid(K_N / 128, B_N / 128);   // (32, 64) = 2048 CTAs
    gemm_mma_kernel<<<grid, NTHR, SMEM_TOTAL>>>();

    rescore_scatter_kernel<<<B_N / 8, 256>>>(X, W);
    update_kernel<<<K_N, 256>>>(W, MA, REL, NC, out);
    scan_kernel<<<1, 1024>>>(out);
    addnode_kernel<<<K_N, 256>>>(out);
}

// round 16
// speedup vs baseline: 1.4138x; 1.4138x over previous
#include <cuda_runtime.h>
#include <cuda_fp16.h>
#include <math.h>
#include <stdint.h>

#define B_N 8192
#define K_N 4096
#define D_N 512
#define NCAND 64           // 2 per 128-node block
#define NSEL 8             // global top-8 rescored exactly

static constexpr float LR     = 0.3f;
static constexpr float AT     = 0.9f;
static constexpr float DSBETA = 1e-4f;
static constexpr float EPS_DS = 0.01f;

// ---------------- scratch (device globals) ----------------
__device__ __half g_xh[B_N * D_N];
__device__ __half g_wh[K_N * D_N];
__device__ float g_xsq[B_N];
__device__ float g_wsq[K_N];
__device__ float g_relsum[K_N];
__device__ int   g_cand_idx[B_N * NCAND];
__device__ float g_cand_val[B_N * NCAND];
__device__ float g_cnt[K_N];
__device__ float g_cntl[K_N];
__device__ float g_sums[K_N * D_N];
__device__ float g_sumsl[K_N * D_N];
__device__ float g_nc1[K_N];
__device__ int   g_lowvalid[K_N];
__device__ int   g_availrank[K_N];
__device__ int   g_validids[K_N];
__device__ float g_loss;
__device__ int   g_nnew;
__device__ int   g_ncreate;

// ---------------- helpers ----------------
__device__ __forceinline__ uint32_t smem_u32(const void* p) {
    uint32_t a;
    asm("{ .reg .u64 t; cvta.to.shared.u64 t, %1; cvt.u32.u64 %0, t; }" : "=r"(a) : "l"(p));
    return a;
}
#define SW128(o) ((o) ^ (((o) >> 3) & 0x70))
#define BETTER(v, k, bv, bk) ((v) > (bv) || ((v) == (bv) && (k) < (bk)))

__device__ __forceinline__ void ldsm_x4(uint32_t (&r)[4], uint32_t addr) {
    asm volatile("ldmatrix.sync.aligned.m8n8.x4.shared.b16 {%0,%1,%2,%3}, [%4];"
                 : "=r"(r[0]), "=r"(r[1]), "=r"(r[2]), "=r"(r[3]) : "r"(addr));
}
__device__ __forceinline__ void mma16816(float (&d)[4], const uint32_t (&a)[4], const uint32_t* b) {
    asm volatile("mma.sync.aligned.m16n8k16.row.col.f32.f16.f16.f32 "
                 "{%0,%1,%2,%3}, {%4,%5,%6,%7}, {%8,%9}, {%0,%1,%2,%3};"
                 : "+f"(d[0]), "+f"(d[1]), "+f"(d[2]), "+f"(d[3])
                 : "r"(a[0]), "r"(a[1]), "r"(a[2]), "r"(a[3]), "r"(b[0]), "r"(b[1]));
}

struct Top2 {
    float v1, v2;
    int   k1, k2;
    __device__ __forceinline__ void init() { v1 = v2 = -1e30f; k1 = k2 = 0x7fffffff; }
    __device__ __forceinline__ void insert(float v, int k) {
        if (BETTER(v, k, v1, k1)) { v2 = v1; k2 = k1; v1 = v; k1 = k; }
        else if (BETTER(v, k, v2, k2)) { v2 = v; k2 = k; }
    }
    __device__ __forceinline__ void merge(float o1, int ok1, float o2, int ok2) {
        if (BETTER(o1, ok1, v1, k1)) {
            if (BETTER(v1, k1, o2, ok2)) { v2 = v1; k2 = k1; }
            else                         { v2 = o2; k2 = ok2; }
            v1 = o1; k1 = ok1;
        } else if (BETTER(o1, ok1, v2, k2)) {
            v2 = o1; k2 = ok1;
        }
    }
};

// ---------------- Kernel S: fused fp16-convert + row stats (warp per row) ----------------
__global__ void split_stats_kernel(const float* __restrict__ X, const float* __restrict__ W,
                                   const float* __restrict__ R) {
    int row  = (blockIdx.x * blockDim.x + threadIdx.x) >> 5;
    int lane = threadIdx.x & 31;
    if (row < B_N) {
        const float4* xr = (const float4*)(X + (size_t)row * D_N);
        float s = 0.f;
#pragma unroll
        for (int i = 0; i < 4; ++i) {
            int d4 = lane + i * 32;
            float4 v = xr[d4];
            s += v.x * v.x + v.y * v.y + v.z * v.z + v.w * v.w;
            float f[4] = {v.x, v.y, v.z, v.w};
            __half h2[4];
#pragma unroll
            for (int j = 0; j < 4; ++j) h2[j] = __float2half_rn(f[j]);
            *(uint64_t*)&g_xh[(size_t)row * D_N + d4 * 4] = *(uint64_t*)h2;
        }
#pragma unroll
        for (int o = 16; o; o >>= 1) s += __shfl_xor_sync(0xFFFFFFFFu, s, o);
        if (lane == 0) g_xsq[row] = s;
    } else {
        int k = row - B_N;
        if (k >= K_N) return;
        const float4* wr = (const float4*)(W + (size_t)k * D_N);
        const float4* rr = (const float4*)(R + (size_t)k * D_N);
        float s1 = 0.f, s2 = 0.f;
#pragma unroll
        for (int i = 0; i < 4; ++i) {
            int d4 = lane + i * 32;
            float4 v = wr[d4];
            float4 u = rr[d4];
            s1 += v.x * v.x + v.y * v.y + v.z * v.z + v.w * v.w;
            s2 += u.x + u.y + u.z + u.w;
            float f[4] = {v.x, v.y, v.z, v.w};
            __half h2[4];
#pragma unroll
            for (int j = 0; j < 4; ++j) h2[j] = __float2half_rn(f[j]);
            *(uint64_t*)&g_wh[(size_t)k * D_N + d4 * 4] = *(uint64_t*)h2;
        }
#pragma unroll
        for (int o = 16; o; o >>= 1) {
            s1 += __shfl_xor_sync(0xFFFFFFFFu, s1, o);
            s2 += __shfl_xor_sync(0xFFFFFFFFu, s2, o);
        }
        if (lane == 0) { g_wsq[k] = s1; g_relsum[k] = s2; }
    }
}

// ---------------- Kernel B: single-term fp16 mma.sync GEMM screen -> per-block top-2 ----------------
// 512 threads, 4x4 warp grid, warp tile 32x32; KC=64 (SW128), 3 stages x 32KB, 8 chunks
// kk loop software-pipelined: fragments double-buffered so LDSM(kk+1) overlaps MMA(kk).
#define KC 64
#define STAGE_BYTES 32768
#define OFF_AH 0
#define OFF_BH 16384
#define NSTAGE 3
#define NCHUNK (D_N / KC)                        // 8
#define SM_STATS (NSTAGE * STAGE_BYTES)          // 98304
#define SMEM_TOTAL (SM_STATS + 1024 + 8192)      // 107520
#define NTHR 512

__device__ __forceinline__ void load_tile_async(uint32_t sdst, const __half* __restrict__ g,
                                                int grow0, int dt, int tid) {
#pragma unroll
    for (int it = 0; it < 2; ++it) {
        int u = tid + it * NTHR;
        int row = u >> 3, c = u & 7;
        const __half* src = g + (size_t)(grow0 + row) * D_N + dt + c * 8;
        uint32_t dst = sdst + SW128(row * 128 + c * 16);
        asm volatile("cp.async.cg.shared.global [%0], [%1], 16;" :: "r"(dst), "l"(src));
    }
}

__global__ __launch_bounds__(NTHR, 2) void gemm_mma_kernel() {
    extern __shared__ char smem[];
    uint32_t sb = smem_u32(smem);
    int tid  = threadIdx.x;
    int lane = tid & 31;
    int warp = tid >> 5;          // 0..15
    int wm = warp >> 2, wn = warp & 3;   // 4 x 4
    int row0 = blockIdx.y * 128;
    int n0   = blockIdx.x * 128;

    float* swsq = (float*)(smem + SM_STATS);
    float* srs  = (float*)(smem + SM_STATS + 512);
    float* rb1  = (float*)(smem + SM_STATS + 1024);
    int*   rk1  = (int*)  (smem + SM_STATS + 3072);
    float* rb2  = (float*)(smem + SM_STATS + 5120);
    int*   rk2  = (int*)  (smem + SM_STATS + 7168);
    if (tid < 128) { swsq[tid] = g_wsq[n0 + tid]; srs[tid] = g_relsum[n0 + tid]; }

    {
        uint32_t st0 = sb;
        load_tile_async(st0 + OFF_AH, g_xh, row0, 0, tid);
        load_tile_async(st0 + OFF_BH, g_wh, n0, 0, tid);
        asm volatile("cp.async.commit_group;" ::: "memory");
        uint32_t st1 = sb + STAGE_BYTES;
        load_tile_async(st1 + OFF_AH, g_xh, row0, KC, tid);
        load_tile_async(st1 + OFF_BH, g_wh, n0, KC, tid);
        asm volatile("cp.async.commit_group;" ::: "memory");
    }

    float acc[2][4][4];
#pragma unroll
    for (int mi = 0; mi < 2; ++mi)
#pragma unroll
        for (int ni = 0; ni < 4; ++ni)
#pragma unroll
            for (int j = 0; j < 4; ++j) acc[mi][ni][j] = 0.f;

    int aRow = lane & 15, aK = lane >> 4;
    int bRowP = 8 * ((lane >> 4) & 1) + (lane & 7);
    int bK    = (lane >> 3) & 1;

    // double-buffered fragments
    uint32_t ah[2][2][4];   // [buf][mi][4]
    uint32_t bh[2][2][4];   // [buf][nj][4]

    for (int c = 0; c < NCHUNK; ++c) {
        if (c < NCHUNK - 1) asm volatile("cp.async.wait_group 1;" ::: "memory");
        else                asm volatile("cp.async.wait_group 0;" ::: "memory");
        __syncthreads();

        if (c + 2 < NCHUNK) {
            uint32_t pst = sb + ((c + 2) % 3) * STAGE_BYTES;
            int dt = (c + 2) * KC;
            load_tile_async(pst + OFF_AH, g_xh, row0, dt, tid);
            load_tile_async(pst + OFF_BH, g_wh, n0, dt, tid);
            asm volatile("cp.async.commit_group;" ::: "memory");
        }

        uint32_t st = sb + (c % 3) * STAGE_BYTES;

        // preload kk=0 fragments into buffer 0
#pragma unroll
        for (int mi = 0; mi < 2; ++mi) {
            uint32_t off = SW128((32 * wm + 16 * mi + aRow) * 128 + aK * 16);
            ldsm_x4(ah[0][mi], st + OFF_AH + off);
        }
#pragma unroll
        for (int nj = 0; nj < 2; ++nj) {
            uint32_t off = SW128((32 * wn + 16 * nj + bRowP) * 128 + bK * 16);
            ldsm_x4(bh[0][nj], st + OFF_BH + off);
        }

#pragma unroll
        for (int kk = 0; kk < KC / 16; ++kk) {
            int cur = kk & 1, nxt = cur ^ 1;
            if (kk < KC / 16 - 1) {
                // issue next step's LDSMs BEFORE this step's MMAs
#pragma unroll
                for (int mi = 0; mi < 2; ++mi) {
                    uint32_t off = SW128((32 * wm + 16 * mi + aRow) * 128 + (2 * (kk + 1) + aK) * 16);
                    ldsm_x4(ah[nxt][mi], st + OFF_AH + off);
                }
#pragma unroll
                for (int nj = 0; nj < 2; ++nj) {
                    uint32_t off = SW128((32 * wn + 16 * nj + bRowP) * 128 + (2 * (kk + 1) + bK) * 16);
                    ldsm_x4(bh[nxt][nj], st + OFF_BH + off);
                }
            }
#pragma unroll
            for (int mi = 0; mi < 2; ++mi)
#pragma unroll
                for (int ni = 0; ni < 4; ++ni) {
                    const uint32_t* pbh = &bh[cur][ni >> 1][(ni & 1) * 2];
                    mma16816(acc[mi][ni], ah[cur][mi], pbh);
                }
        }
    }

    // ---------------- epilogue: act + per-row per-block top-2 ----------------
    const float invD = 1.0f / (float)D_N;
    int t4 = lane >> 2;
#pragma unroll
    for (int mi = 0; mi < 2; ++mi) {
        int r0l = 32 * wm + 16 * mi + t4;
        float xsq0 = g_xsq[row0 + r0l];
        float xsq1 = g_xsq[row0 + r0l + 8];
        Top2 tA, tB;
        tA.init(); tB.init();
#pragma unroll
        for (int ni = 0; ni < 4; ++ni) {
#pragma unroll
            for (int j = 0; j < 2; ++j) {
                int nl = 32 * wn + 8 * ni + 2 * (lane & 3) + j;
                int kg = n0 + nl;
                float wsq = swsq[nl], rs = srs[nl];
                float rsd = rs * invD;
                float d0  = xsq0 + wsq - 2.f * acc[mi][ni][j];
                float a0v = rs / (rs + d0 * rsd + 1e-7f);
                tA.insert(a0v, kg);
                float d1  = xsq1 + wsq - 2.f * acc[mi][ni][2 + j];
                float a1v = rs / (rs + d1 * rsd + 1e-7f);
                tB.insert(a1v, kg);
            }
        }
#pragma unroll
        for (int o = 1; o <= 2; o <<= 1) {
            float o1 = __shfl_xor_sync(0xFFFFFFFFu, tA.v1, o);
            int  ok1 = __shfl_xor_sync(0xFFFFFFFFu, tA.k1, o);
            float o2 = __shfl_xor_sync(0xFFFFFFFFu, tA.v2, o);
            int  ok2 = __shfl_xor_sync(0xFFFFFFFFu, tA.k2, o);
            tA.merge(o1, ok1, o2, ok2);
            o1 = __shfl_xor_sync(0xFFFFFFFFu, tB.v1, o);
            ok1 = __shfl_xor_sync(0xFFFFFFFFu, tB.k1, o);
            o2 = __shfl_xor_sync(0xFFFFFFFFu, tB.v2, o);
            ok2 = __shfl_xor_sync(0xFFFFFFFFu, tB.k2, o);
            tB.merge(o1, ok1, o2, ok2);
        }
        if ((lane & 3) == 0) {
            rb1[r0l * 4 + wn] = tA.v1;  rk1[r0l * 4 + wn] = tA.k1;
            rb2[r0l * 4 + wn] = tA.v2;  rk2[r0l * 4 + wn] = tA.k2;
            rb1[(r0l + 8) * 4 + wn] = tB.v1;  rk1[(r0l + 8) * 4 + wn] = tB.k1;
            rb2[(r0l + 8) * 4 + wn] = tB.v2;  rk2[(r0l + 8) * 4 + wn] = tB.k2;
        }
    }
    __syncthreads();
    if (tid < 128) {
        Top2 t;
        t.v1 = rb1[tid * 4]; t.k1 = rk1[tid * 4];
        t.v2 = rb2[tid * 4]; t.k2 = rk2[tid * 4];
#pragma unroll
        for (int j = 1; j < 4; ++j)
            t.merge(rb1[tid * 4 + j], rk1[tid * 4 + j], rb2[tid * 4 + j], rk2[tid * 4 + j]);
        size_t base = (size_t)(row0 + tid) * NCAND + blockIdx.x * 2;
        g_cand_idx[base]     = t.k1;  g_cand_val[base]     = t.v1;
        g_cand_idx[base + 1] = t.k2;  g_cand_val[base + 1] = t.v2;
    }
}

// ---------------- Kernel R: fused merge(top-8) + exact fp32 rescore + scatter ----------------
__global__ __launch_bounds__(256) void rescore_scatter_kernel(const float* __restrict__ X,
                                                              const float* __restrict__ W) {
    int warp = threadIdx.x >> 5, lane = threadIdx.x & 31;
    int b = blockIdx.x * 8 + warp;
    size_t cbase = (size_t)b * NCAND;
    float v0 = g_cand_val[cbase + lane],  v1 = g_cand_val[cbase + 32 + lane];
    int   k0 = g_cand_idx[cbase + lane],  k1 = g_cand_idx[cbase + 32 + lane];

    int sel[NSEL];
#pragma unroll
    for (int r = 0; r < NSEL; ++r) {
        float bv; int bk;
        if (BETTER(v0, k0, v1, k1)) { bv = v0; bk = k0; } else { bv = v1; bk = k1; }
#pragma unroll
        for (int o = 16; o; o >>= 1) {
            float ov = __shfl_xor_sync(0xFFFFFFFFu, bv, o);
            int   ok = __shfl_xor_sync(0xFFFFFFFFu, bk, o);
            if (BETTER(ov, ok, bv, bk)) { bv = ov; bk = ok; }
        }
        sel[r] = bk;   // all lanes have it
        if (v0 == bv && k0 == bk) { v0 = -1e30f; k0 = 0x7fffffff; }
        else if (v1 == bv && k1 == bk) { v1 = -1e30f; k1 = 0x7fffffff; }
    }

    const float4* xr = (const float4*)(X + (size_t)b * D_N);
    float4 xv[4];
#pragma unroll
    for (int i = 0; i < 4; ++i) xv[i] = xr[lane + i * 32];

    float xsq = g_xsq[b];
    const float invD = 1.0f / (float)D_N;

    float bv = -1e30f;
    int   bk = 0x7fffffff;
#pragma unroll
    for (int r = 0; r < NSEL; ++r) {
        int k = sel[r];
        const float4* wr = (const float4*)(W + (size_t)k * D_N);
        float acc = 0.f;
#pragma unroll
        for (int i = 0; i < 4; ++i) {
            float4 wv = wr[lane + i * 32];
            acc = fmaf(xv[i].x, wv.x, acc); acc = fmaf(xv[i].y, wv.y, acc);
            acc = fmaf(xv[i].z, wv.z, acc); acc = fmaf(xv[i].w, wv.w, acc);
        }
#pragma unroll
        for (int o = 16; o; o >>= 1) acc += __shfl_xor_sync(0xFFFFFFFFu, acc, o);

        float wsq = g_wsq[k], rs = g_relsum[k];
        float rsd  = rs * invD;
        float dist = xsq + wsq - 2.f * acc;
        float act  = rs / (rs + dist * rsd + 1e-7f);
        if (BETTER(act, k, bv, bk)) { bv = act; bk = k; }
    }

    int high = (bv >= AT) ? 1 : 0;
    float* sums = high ? g_sums : g_sumsl;
    float* cnt  = high ? g_cnt  : g_cntl;
    if (lane == 0) atomicAdd(&cnt[bk], 1.0f);
    float* dst = sums + (size_t)bk * D_N;
#pragma unroll
    for (int i = 0; i < 4; ++i) {
        int d = (lane + i * 32) * 4;
        atomicAdd(&dst[d + 0], xv[i].x);
        atomicAdd(&dst[d + 1], xv[i].y);
        atomicAdd(&dst[d + 2], xv[i].z);
        atomicAdd(&dst[d + 3], xv[i].w);
    }
}

// ---------------- Kernel D: per-node high-branch update ----------------
__global__ __launch_bounds__(256) void update_kernel(
    const float* __restrict__ W, const float* __restrict__ MA,
    const float* __restrict__ REL, const float* __restrict__ NC,
    float* __restrict__ out)
{
    int k = blockIdx.x;
    int t = threadIdx.x;

    float cntk = g_cnt[k];
    int   upd  = cntk > 0.f;
    float inv  = upd ? 1.f / cntk : 1.f;

    float* outw   = out + 1;
    float* outma  = out + 1 + (size_t)K_N * D_N;
    float* outrel = out + 1 + 2 * (size_t)K_N * D_N;
    float* outnc  = out + 1 + 3 * (size_t)K_N * D_N;

    const float a = LR * DSBETA;

    float wv[2], meanv[2], ma1v[2];
    float mx = -1e30f, mn = 1e30f, sm = 0.f, lsum = 0.f;
#pragma unroll
    for (int e = 0; e < 2; e++) {
        int d = t + e * 256;
        size_t off = (size_t)k * D_N + d;
        float w  = W[off];
        float m  = upd ? g_sums[off] * inv : 0.f;
        float ma = MA[off];
        float m1 = upd ? (a * fabsf(m - w) + (1.f - a) * ma) : ma;
        wv[e] = w; meanv[e] = m; ma1v[e] = m1;
        mx = fmaxf(mx, m1); mn = fminf(mn, m1); sm += m1;
        if (upd) lsum += LR * (m - w);
    }

    __shared__ float smax[8], smin[8], ssum[8], sls[8];
#pragma unroll
    for (int o = 16; o; o >>= 1) {
        mx   = fmaxf(mx, __shfl_xor_sync(0xFFFFFFFFu, mx, o));
        mn   = fminf(mn, __shfl_xor_sync(0xFFFFFFFFu, mn, o));
        sm  += __shfl_xor_sync(0xFFFFFFFFu, sm, o);
        lsum += __shfl_xor_sync(0xFFFFFFFFu, lsum, o);
    }
    int wrp = t >> 5, lane = t & 31;
    if (lane == 0) { smax[wrp] = mx; smin[wrp] = mn; ssum[wrp] = sm; sls[wrp] = lsum; }
    __syncthreads();
    mx = smax[0]; mn = smin[0]; sm = 0.f; float ltot = 0.f;
#pragma unroll
    for (int wgi = 0; wgi < 8; wgi++) {
        mx = fmaxf(mx, smax[wgi]); mn = fminf(mn, smin[wgi]);
        sm += ssum[wgi]; ltot += sls[wgi];
    }

    float av     = sm * (1.f / (float)D_N);
    float idenom = 1.f / (EPS_DS * (mx - mn));

#pragma unroll
    for (int e = 0; e < 2; e++) {
        int d = t + e * 256;
        size_t off = (size_t)k * D_N + d;
        float m1  = ma1v[e];
        float rel = upd ? 1.f / (1.f + __expf((m1 - av) * idenom)) : REL[off];
        float w1  = upd ? wv[e] + LR * (meanv[e] - wv[e]) : wv[e];
        outw[off]  = w1;
        outma[off] = m1;
        outrel[off] = rel;
    }
    if (t == 0) {
        float nc1 = upd ? 1.f : NC[k];
        g_nc1[k] = nc1;
        outnc[k] = nc1;
        g_lowvalid[k] = (g_cntl[k] > 0.f) ? 1 : 0;
        if (upd) atomicAdd(&g_loss, ltot);
    }
}

// ---------------- Kernel E: single-block scan for add_node ----------------
__global__ void scan_kernel(float* __restrict__ out) {
    __shared__ int s_lv[1024];
    __shared__ int s_av[1024];
    int t = threadIdx.x;
    int lvloc[4], avloc[4];
    int lv = 0, av = 0;
#pragma unroll
    for (int j = 0; j < 4; j++) {
        int k = t * 4 + j;
        int l  = g_lowvalid[k];
        int a2 = (g_nc1[k] == 0.f) ? 1 : 0;
        lvloc[j] = l; avloc[j] = a2;
        lv += l; av += a2;
    }
    s_lv[t] = lv; s_av[t] = av;
    __syncthreads();
    for (int o = 1; o < 1024; o <<= 1) {
        int a = 0, b2 = 0;
        if (t >= o) { a = s_lv[t - o]; b2 = s_av[t - o]; }
        __syncthreads();
        if (t >= o) { s_lv[t] += a; s_av[t] += b2; }
        __syncthreads();
    }
    int nnew   = s_lv[1023];
    int navail = s_av[1023];
    int exlv = s_lv[t] - lv;
    int exav = s_av[t] - av;
#pragma unroll
    for (int j = 0; j < 4; j++) {
        int k = t * 4 + j;
        if (lvloc[j]) { g_validids[exlv] = k; exlv++; }
        if (avloc[j]) { g_availrank[k] = exav; exav++; }
    }
    if (t == 0) {
        g_nnew = nnew;
        g_ncreate = nnew < navail ? nnew : navail;
        out[0] = g_loss / (float)B_N;
    }
}

// ---------------- Kernel F: add_node slot fill ----------------
__global__ void addnode_kernel(float* __restrict__ out) {
    int k = blockIdx.x;
    if (g_nc1[k] != 0.f) return;
    int r = g_availrank[k];
    int ncreate = g_ncreate;
    if (r >= ncreate) return;
    int src = g_validids[g_nnew - ncreate + r];
    float inv = 1.f / g_cntl[src];

    float* outw   = out + 1;
    float* outma  = out + 1 + (size_t)K_N * D_N;
    float* outrel = out + 1 + 2 * (size_t)K_N * D_N;
    float* outnc  = out + 1 + 3 * (size_t)K_N * D_N;

    for (int d = threadIdx.x; d < D_N; d += blockDim.x) {
        size_t off = (size_t)k * D_N + d;
        outw[off]   = g_sumsl[(size_t)src * D_N + d] * inv;
        outma[off]  = 0.f;
        outrel[off] = 1.f;
    }
    if (threadIdx.x == 0) outnc[k] = 1.f;
}

// ---------------- launch ----------------
extern "C" void kernel_launch(void* const* d_in, const int* in_sizes, int n_in,
                              void* d_out, int out_size) {
    const float* X   = (const float*)d_in[0];
    const float* W   = (const float*)d_in[1];
    const float* MA  = (const float*)d_in[2];
    const float* REL = (const float*)d_in[3];
    const float* NC  = (const float*)d_in[4];
    float* out = (float*)d_out;

    void* p;
    cudaGetSymbolAddress(&p, g_cnt);   cudaMemsetAsync(p, 0, K_N * sizeof(float));
    cudaGetSymbolAddress(&p, g_cntl);  cudaMemsetAsync(p, 0, K_N * sizeof(float));
    cudaGetSymbolAddress(&p, g_sums);  cudaMemsetAsync(p, 0, (size_t)K_N * D_N * sizeof(float));
    cudaGetSymbolAddress(&p, g_sumsl); cudaMemsetAsync(p, 0, (size_t)K_N * D_N * sizeof(float));
    cudaGetSymbolAddress(&p, g_loss);  cudaMemsetAsync(p, 0, sizeof(float));

    split_stats_kernel<<<(B_N + K_N) / 8, 256>>>(X, W, REL);

    cudaFuncSetAttribute(gemm_mma_kernel, cudaFuncAttributeMaxDynamicSharedMemorySize, SMEM_TOTAL);
    dim3 grid(K_N / 128, B_N / 128);   // (32, 64) = 2048 CTAs
    gemm_mma_kernel<<<grid, NTHR, SMEM_TOTAL>>>();

    rescore_scatter_kernel<<<B_N / 8, 256>>>(X, W);
    update_kernel<<<K_N, 256>>>(W, MA, REL, NC, out);
    scan_kernel<<<1, 1024>>>(out);
    addnode_kernel<<<K_N, 256>>>(out);
}

// round 17
// speedup vs baseline: 1.4960x; 1.0581x over previous
#include <cuda_runtime.h>
#include <cuda_fp16.h>
#include <math.h>
#include <stdint.h>

#define B_N 8192
#define K_N 4096
#define D_N 512
#define NCAND 64           // 2 per 128-node block
#define NSEL 8             // global top-8 rescored exactly

static constexpr float LR     = 0.3f;
static constexpr float AT     = 0.9f;
static constexpr float DSBETA = 1e-4f;
static constexpr float EPS_DS = 0.01f;

// ---------------- scratch (device globals) ----------------
__device__ __half g_xh[B_N * D_N];
__device__ __half g_wh[K_N * D_N];
__device__ float g_xsq[B_N];
__device__ float g_wsq[K_N];
__device__ float g_relsum[K_N];
__device__ int   g_cand_idx[B_N * NCAND];
__device__ float g_cand_val[B_N * NCAND];
__device__ float g_cnt[K_N];
__device__ float g_cntl[K_N];
__device__ float g_sums[K_N * D_N];
__device__ float g_sumsl[K_N * D_N];
__device__ float g_nc1[K_N];
__device__ int   g_lowvalid[K_N];
__device__ int   g_availrank[K_N];
__device__ int   g_validids[K_N];
__device__ float g_loss;
__device__ int   g_nnew;
__device__ int   g_ncreate;

// ---------------- helpers ----------------
__device__ __forceinline__ uint32_t smem_u32(const void* p) {
    uint32_t a;
    asm("{ .reg .u64 t; cvta.to.shared.u64 t, %1; cvt.u32.u64 %0, t; }" : "=r"(a) : "l"(p));
    return a;
}
#define SW128(o) ((o) ^ (((o) >> 3) & 0x70))
#define BETTER(v, k, bv, bk) ((v) > (bv) || ((v) == (bv) && (k) < (bk)))

__device__ __forceinline__ void ldsm_x4(uint32_t (&r)[4], uint32_t addr) {
    asm volatile("ldmatrix.sync.aligned.m8n8.x4.shared.b16 {%0,%1,%2,%3}, [%4];"
                 : "=r"(r[0]), "=r"(r[1]), "=r"(r[2]), "=r"(r[3]) : "r"(addr));
}
// fp16-accumulator HMMA: D(f16x2 x2) = A*B^T + D
__device__ __forceinline__ void mma16816h(uint32_t (&d)[2], const uint32_t (&a)[4], const uint32_t* b) {
    asm volatile("mma.sync.aligned.m16n8k16.row.col.f16.f16.f16.f16 "
                 "{%0,%1}, {%2,%3,%4,%5}, {%6,%7}, {%0,%1};"
                 : "+r"(d[0]), "+r"(d[1])
                 : "r"(a[0]), "r"(a[1]), "r"(a[2]), "r"(a[3]), "r"(b[0]), "r"(b[1]));
}

struct Top2 {
    float v1, v2;
    int   k1, k2;
    __device__ __forceinline__ void init() { v1 = v2 = -1e30f; k1 = k2 = 0x7fffffff; }
    __device__ __forceinline__ void insert(float v, int k) {
        if (BETTER(v, k, v1, k1)) { v2 = v1; k2 = k1; v1 = v; k1 = k; }
        else if (BETTER(v, k, v2, k2)) { v2 = v; k2 = k; }
    }
    __device__ __forceinline__ void merge(float o1, int ok1, float o2, int ok2) {
        if (BETTER(o1, ok1, v1, k1)) {
            if (BETTER(v1, k1, o2, ok2)) { v2 = v1; k2 = k1; }
            else                         { v2 = o2; k2 = ok2; }
            v1 = o1; k1 = ok1;
        } else if (BETTER(o1, ok1, v2, k2)) {
            v2 = o1; k2 = ok1;
        }
    }
};

// ---------------- Kernel S: fused fp16-convert + row stats (warp per row) ----------------
__global__ void split_stats_kernel(const float* __restrict__ X, const float* __restrict__ W,
                                   const float* __restrict__ R) {
    int row  = (blockIdx.x * blockDim.x + threadIdx.x) >> 5;
    int lane = threadIdx.x & 31;
    if (row < B_N) {
        const float4* xr = (const float4*)(X + (size_t)row * D_N);
        float s = 0.f;
#pragma unroll
        for (int i = 0; i < 4; ++i) {
            int d4 = lane + i * 32;
            float4 v = xr[d4];
            s += v.x * v.x + v.y * v.y + v.z * v.z + v.w * v.w;
            float f[4] = {v.x, v.y, v.z, v.w};
            __half h2[4];
#pragma unroll
            for (int j = 0; j < 4; ++j) h2[j] = __float2half_rn(f[j]);
            *(uint64_t*)&g_xh[(size_t)row * D_N + d4 * 4] = *(uint64_t*)h2;
        }
#pragma unroll
        for (int o = 16; o; o >>= 1) s += __shfl_xor_sync(0xFFFFFFFFu, s, o);
        if (lane == 0) g_xsq[row] = s;
    } else {
        int k = row - B_N;
        if (k >= K_N) return;
        const float4* wr = (const float4*)(W + (size_t)k * D_N);
        const float4* rr = (const float4*)(R + (size_t)k * D_N);
        float s1 = 0.f, s2 = 0.f;
#pragma unroll
        for (int i = 0; i < 4; ++i) {
            int d4 = lane + i * 32;
            float4 v = wr[d4];
            float4 u = rr[d4];
            s1 += v.x * v.x + v.y * v.y + v.z * v.z + v.w * v.w;
            s2 += u.x + u.y + u.z + u.w;
            float f[4] = {v.x, v.y, v.z, v.w};
            __half h2[4];
#pragma unroll
            for (int j = 0; j < 4; ++j) h2[j] = __float2half_rn(f[j]);
            *(uint64_t*)&g_wh[(size_t)k * D_N + d4 * 4] = *(uint64_t*)h2;
        }
#pragma unroll
        for (int o = 16; o; o >>= 1) {
            s1 += __shfl_xor_sync(0xFFFFFFFFu, s1, o);
            s2 += __shfl_xor_sync(0xFFFFFFFFu, s2, o);
        }
        if (lane == 0) { g_wsq[k] = s1; g_relsum[k] = s2; }
    }
}

// ---------------- Kernel B: fp16-acc mma.sync GEMM screen -> per-block top-2 ----------------
// 512 threads, 4x4 warp grid, warp tile 32x32; KC=64 (SW128), 3 stages x 32KB, 8 chunks
// Same structure as the fp32-acc version; only accumulator type differs.
#define KC 64
#define STAGE_BYTES 32768
#define OFF_AH 0
#define OFF_BH 16384
#define NSTAGE 3
#define NCHUNK (D_N / KC)                        // 8
#define SM_STATS (NSTAGE * STAGE_BYTES)          // 98304
#define SMEM_TOTAL (SM_STATS + 1024 + 8192)      // 107520
#define NTHR 512

__device__ __forceinline__ void load_tile_async(uint32_t sdst, const __half* __restrict__ g,
                                                int grow0, int dt, int tid) {
#pragma unroll
    for (int it = 0; it < 2; ++it) {
        int u = tid + it * NTHR;
        int row = u >> 3, c = u & 7;
        const __half* src = g + (size_t)(grow0 + row) * D_N + dt + c * 8;
        uint32_t dst = sdst + SW128(row * 128 + c * 16);
        asm volatile("cp.async.cg.shared.global [%0], [%1], 16;" :: "r"(dst), "l"(src));
    }
}

__global__ __launch_bounds__(NTHR, 2) void gemm_mma_kernel() {
    extern __shared__ char smem[];
    uint32_t sb = smem_u32(smem);
    int tid  = threadIdx.x;
    int lane = tid & 31;
    int warp = tid >> 5;          // 0..15
    int wm = warp >> 2, wn = warp & 3;   // 4 x 4
    int row0 = blockIdx.y * 128;
    int n0   = blockIdx.x * 128;

    float* swsq = (float*)(smem + SM_STATS);
    float* srs  = (float*)(smem + SM_STATS + 512);
    float* rb1  = (float*)(smem + SM_STATS + 1024);
    int*   rk1  = (int*)  (smem + SM_STATS + 3072);
    float* rb2  = (float*)(smem + SM_STATS + 5120);
    int*   rk2  = (int*)  (smem + SM_STATS + 7168);
    if (tid < 128) { swsq[tid] = g_wsq[n0 + tid]; srs[tid] = g_relsum[n0 + tid]; }

    {
        uint32_t st0 = sb;
        load_tile_async(st0 + OFF_AH, g_xh, row0, 0, tid);
        load_tile_async(st0 + OFF_BH, g_wh, n0, 0, tid);
        asm volatile("cp.async.commit_group;" ::: "memory");
        uint32_t st1 = sb + STAGE_BYTES;
        load_tile_async(st1 + OFF_AH, g_xh, row0, KC, tid);
        load_tile_async(st1 + OFF_BH, g_wh, n0, KC, tid);
        asm volatile("cp.async.commit_group;" ::: "memory");
    }

    uint32_t acc[2][4][2];      // fp16x2 accumulators (2 regs per mma)
#pragma unroll
    for (int mi = 0; mi < 2; ++mi)
#pragma unroll
        for (int ni = 0; ni < 4; ++ni)
#pragma unroll
            for (int j = 0; j < 2; ++j) acc[mi][ni][j] = 0u;

    int aRow = lane & 15, aK = lane >> 4;
    int bRowP = 8 * ((lane >> 4) & 1) + (lane & 7);
    int bK    = (lane >> 3) & 1;

    // double-buffered fragments
    uint32_t ah[2][2][4];   // [buf][mi][4]
    uint32_t bh[2][2][4];   // [buf][nj][4]

    for (int c = 0; c < NCHUNK; ++c) {
        if (c < NCHUNK - 1) asm volatile("cp.async.wait_group 1;" ::: "memory");
        else                asm volatile("cp.async.wait_group 0;" ::: "memory");
        __syncthreads();

        if (c + 2 < NCHUNK) {
            uint32_t pst = sb + ((c + 2) % 3) * STAGE_BYTES;
            int dt = (c + 2) * KC;
            load_tile_async(pst + OFF_AH, g_xh, row0, dt, tid);
            load_tile_async(pst + OFF_BH, g_wh, n0, dt, tid);
            asm volatile("cp.async.commit_group;" ::: "memory");
        }

        uint32_t st = sb + (c % 3) * STAGE_BYTES;

        // preload kk=0 fragments into buffer 0
#pragma unroll
        for (int mi = 0; mi < 2; ++mi) {
            uint32_t off = SW128((32 * wm + 16 * mi + aRow) * 128 + aK * 16);
            ldsm_x4(ah[0][mi], st + OFF_AH + off);
        }
#pragma unroll
        for (int nj = 0; nj < 2; ++nj) {
            uint32_t off = SW128((32 * wn + 16 * nj + bRowP) * 128 + bK * 16);
            ldsm_x4(bh[0][nj], st + OFF_BH + off);
        }

#pragma unroll
        for (int kk = 0; kk < KC / 16; ++kk) {
            int cur = kk & 1, nxt = cur ^ 1;
            if (kk < KC / 16 - 1) {
#pragma unroll
                for (int mi = 0; mi < 2; ++mi) {
                    uint32_t off = SW128((32 * wm + 16 * mi + aRow) * 128 + (2 * (kk + 1) + aK) * 16);
                    ldsm_x4(ah[nxt][mi], st + OFF_AH + off);
                }
#pragma unroll
                for (int nj = 0; nj < 2; ++nj) {
                    uint32_t off = SW128((32 * wn + 16 * nj + bRowP) * 128 + (2 * (kk + 1) + bK) * 16);
                    ldsm_x4(bh[nxt][nj], st + OFF_BH + off);
                }
            }
#pragma unroll
            for (int mi = 0; mi < 2; ++mi)
#pragma unroll
                for (int ni = 0; ni < 4; ++ni) {
                    const uint32_t* pbh = &bh[cur][ni >> 1][(ni & 1) * 2];
                    mma16816h(acc[mi][ni], ah[cur][mi], pbh);
                }
        }
    }

    // ---------------- epilogue: unpack fp16 acc + act + per-row per-block top-2 ----------------
    const float invD = 1.0f / (float)D_N;
    int t4 = lane >> 2;
#pragma unroll
    for (int mi = 0; mi < 2; ++mi) {
        int r0l = 32 * wm + 16 * mi + t4;
        float xsq0 = g_xsq[row0 + r0l];
        float xsq1 = g_xsq[row0 + r0l + 8];
        Top2 tA, tB;
        tA.init(); tB.init();
#pragma unroll
        for (int ni = 0; ni < 4; ++ni) {
            __half2 h0 = *(__half2*)&acc[mi][ni][0];   // row t4:   cols j=0,1
            __half2 h1 = *(__half2*)&acc[mi][ni][1];   // row t4+8: cols j=0,1
            float d0v[2] = { __low2float(h0), __high2float(h0) };
            float d1v[2] = { __low2float(h1), __high2float(h1) };
#pragma unroll
            for (int j = 0; j < 2; ++j) {
                int nl = 32 * wn + 8 * ni + 2 * (lane & 3) + j;
                int kg = n0 + nl;
                float wsq = swsq[nl], rs = srs[nl];
                float rsd = rs * invD;
                float dd0 = xsq0 + wsq - 2.f * d0v[j];
                float a0v = rs / (rs + dd0 * rsd + 1e-7f);
                tA.insert(a0v, kg);
                float dd1 = xsq1 + wsq - 2.f * d1v[j];
                float a1v = rs / (rs + dd1 * rsd + 1e-7f);
                tB.insert(a1v, kg);
            }
        }
#pragma unroll
        for (int o = 1; o <= 2; o <<= 1) {
            float o1 = __shfl_xor_sync(0xFFFFFFFFu, tA.v1, o);
            int  ok1 = __shfl_xor_sync(0xFFFFFFFFu, tA.k1, o);
            float o2 = __shfl_xor_sync(0xFFFFFFFFu, tA.v2, o);
            int  ok2 = __shfl_xor_sync(0xFFFFFFFFu, tA.k2, o);
            tA.merge(o1, ok1, o2, ok2);
            o1 = __shfl_xor_sync(0xFFFFFFFFu, tB.v1, o);
            ok1 = __shfl_xor_sync(0xFFFFFFFFu, tB.k1, o);
            o2 = __shfl_xor_sync(0xFFFFFFFFu, tB.v2, o);
            ok2 = __shfl_xor_sync(0xFFFFFFFFu, tB.k2, o);
            tB.merge(o1, ok1, o2, ok2);
        }
        if ((lane & 3) == 0) {
            rb1[r0l * 4 + wn] = tA.v1;  rk1[r0l * 4 + wn] = tA.k1;
            rb2[r0l * 4 + wn] = tA.v2;  rk2[r0l * 4 + wn] = tA.k2;
            rb1[(r0l + 8) * 4 + wn] = tB.v1;  rk1[(r0l + 8) * 4 + wn] = tB.k1;
            rb2[(r0l + 8) * 4 + wn] = tB.v2;  rk2[(r0l + 8) * 4 + wn] = tB.k2;
        }
    }
    __syncthreads();
    if (tid < 128) {
        Top2 t;
        t.v1 = rb1[tid * 4]; t.k1 = rk1[tid * 4];
        t.v2 = rb2[tid * 4]; t.k2 = rk2[tid * 4];
#pragma unroll
        for (int j = 1; j < 4; ++j)
            t.merge(rb1[tid * 4 + j], rk1[tid * 4 + j], rb2[tid * 4 + j], rk2[tid * 4 + j]);
        size_t base = (size_t)(row0 + tid) * NCAND + blockIdx.x * 2;
        g_cand_idx[base]     = t.k1;  g_cand_val[base]     = t.v1;
        g_cand_idx[base + 1] = t.k2;  g_cand_val[base + 1] = t.v2;
    }
}

// ---------------- Kernel R: fused merge(top-8) + exact fp32 rescore + scatter ----------------
__global__ __launch_bounds__(256) void rescore_scatter_kernel(const float* __restrict__ X,
                                                              const float* __restrict__ W) {
    int warp = threadIdx.x >> 5, lane = threadIdx.x & 31;
    int b = blockIdx.x * 8 + warp;
    size_t cbase = (size_t)b * NCAND;
    float v0 = g_cand_val[cbase + lane],  v1 = g_cand_val[cbase + 32 + lane];
    int   k0 = g_cand_idx[cbase + lane],  k1 = g_cand_idx[cbase + 32 + lane];

    int sel[NSEL];
#pragma unroll
    for (int r = 0; r < NSEL; ++r) {
        float bv; int bk;
        if (BETTER(v0, k0, v1, k1)) { bv = v0; bk = k0; } else { bv = v1; bk = k1; }
#pragma unroll
        for (int o = 16; o; o >>= 1) {
            float ov = __shfl_xor_sync(0xFFFFFFFFu, bv, o);
            int   ok = __shfl_xor_sync(0xFFFFFFFFu, bk, o);
            if (BETTER(ov, ok, bv, bk)) { bv = ov; bk = ok; }
        }
        sel[r] = bk;
        if (v0 == bv && k0 == bk) { v0 = -1e30f; k0 = 0x7fffffff; }
        else if (v1 == bv && k1 == bk) { v1 = -1e30f; k1 = 0x7fffffff; }
    }

    const float4* xr = (const float4*)(X + (size_t)b * D_N);
    float4 xv[4];
#pragma unroll
    for (int i = 0; i < 4; ++i) xv[i] = xr[lane + i * 32];

    float xsq = g_xsq[b];
    const float invD = 1.0f / (float)D_N;

    float bv = -1e30f;
    int   bk = 0x7fffffff;
#pragma unroll
    for (int r = 0; r < NSEL; ++r) {
        int k = sel[r];
        const float4* wr = (const float4*)(W + (size_t)k * D_N);
        float acc = 0.f;
#pragma unroll
        for (int i = 0; i < 4; ++i) {
            float4 wv = wr[lane + i * 32];
            acc = fmaf(xv[i].x, wv.x, acc); acc = fmaf(xv[i].y, wv.y, acc);
            acc = fmaf(xv[i].z, wv.z, acc); acc = fmaf(xv[i].w, wv.w, acc);
        }
#pragma unroll
        for (int o = 16; o; o >>= 1) acc += __shfl_xor_sync(0xFFFFFFFFu, acc, o);

        float wsq = g_wsq[k], rs = g_relsum[k];
        float rsd  = rs * invD;
        float dist = xsq + wsq - 2.f * acc;
        float act  = rs / (rs + dist * rsd + 1e-7f);
        if (BETTER(act, k, bv, bk)) { bv = act; bk = k; }
    }

    int high = (bv >= AT) ? 1 : 0;
    float* sums = high ? g_sums : g_sumsl;
    float* cnt  = high ? g_cnt  : g_cntl;
    if (lane == 0) atomicAdd(&cnt[bk], 1.0f);
    float* dst = sums + (size_t)bk * D_N;
#pragma unroll
    for (int i = 0; i < 4; ++i) {
        int d = (lane + i * 32) * 4;
        atomicAdd(&dst[d + 0], xv[i].x);
        atomicAdd(&dst[d + 1], xv[i].y);
        atomicAdd(&dst[d + 2], xv[i].z);
        atomicAdd(&dst[d + 3], xv[i].w);
    }
}

// ---------------- Kernel D: per-node high-branch update ----------------
__global__ __launch_bounds__(256) void update_kernel(
    const float* __restrict__ W, const float* __restrict__ MA,
    const float* __restrict__ REL, const float* __restrict__ NC,
    float* __restrict__ out)
{
    int k = blockIdx.x;
    int t = threadIdx.x;

    float cntk = g_cnt[k];
    int   upd  = cntk > 0.f;
    float inv  = upd ? 1.f / cntk : 1.f;

    float* outw   = out + 1;
    float* outma  = out + 1 + (size_t)K_N * D_N;
    float* outrel = out + 1 + 2 * (size_t)K_N * D_N;
    float* outnc  = out + 1 + 3 * (size_t)K_N * D_N;

    const float a = LR * DSBETA;

    float wv[2], meanv[2], ma1v[2];
    float mx = -1e30f, mn = 1e30f, sm = 0.f, lsum = 0.f;
#pragma unroll
    for (int e = 0; e < 2; e++) {
        int d = t + e * 256;
        size_t off = (size_t)k * D_N + d;
        float w  = W[off];
        float m  = upd ? g_sums[off] * inv : 0.f;
        float ma = MA[off];
        float m1 = upd ? (a * fabsf(m - w) + (1.f - a) * ma) : ma;
        wv[e] = w; meanv[e] = m; ma1v[e] = m1;
        mx = fmaxf(mx, m1); mn = fminf(mn, m1); sm += m1;
        if (upd) lsum += LR * (m - w);
    }

    __shared__ float smax[8], smin[8], ssum[8], sls[8];
#pragma unroll
    for (int o = 16; o; o >>= 1) {
        mx   = fmaxf(mx, __shfl_xor_sync(0xFFFFFFFFu, mx, o));
        mn   = fminf(mn, __shfl_xor_sync(0xFFFFFFFFu, mn, o));
        sm  += __shfl_xor_sync(0xFFFFFFFFu, sm, o);
        lsum += __shfl_xor_sync(0xFFFFFFFFu, lsum, o);
    }
    int wrp = t >> 5, lane = t & 31;
    if (lane == 0) { smax[wrp] = mx; smin[wrp] = mn; ssum[wrp] = sm; sls[wrp] = lsum; }
    __syncthreads();
    mx = smax[0]; mn = smin[0]; sm = 0.f; float ltot = 0.f;
#pragma unroll
    for (int wgi = 0; wgi < 8; wgi++) {
        mx = fmaxf(mx, smax[wgi]); mn = fminf(mn, smin[wgi]);
        sm += ssum[wgi]; ltot += sls[wgi];
    }

    float av     = sm * (1.f / (float)D_N);
    float idenom = 1.f / (EPS_DS * (mx - mn));

#pragma unroll
    for (int e = 0; e < 2; e++) {
        int d = t + e * 256;
        size_t off = (size_t)k * D_N + d;
        float m1  = ma1v[e];
        float rel = upd ? 1.f / (1.f + __expf((m1 - av) * idenom)) : REL[off];
        float w1  = upd ? wv[e] + LR * (meanv[e] - wv[e]) : wv[e];
        outw[off]  = w1;
        outma[off] = m1;
        outrel[off] = rel;
    }
    if (t == 0) {
        float nc1 = upd ? 1.f : NC[k];
        g_nc1[k] = nc1;
        outnc[k] = nc1;
        g_lowvalid[k] = (g_cntl[k] > 0.f) ? 1 : 0;
        if (upd) atomicAdd(&g_loss, ltot);
    }
}

// ---------------- Kernel E: single-block scan for add_node ----------------
__global__ void scan_kernel(float* __restrict__ out) {
    __shared__ int s_lv[1024];
    __shared__ int s_av[1024];
    int t = threadIdx.x;
    int lvloc[4], avloc[4];
    int lv = 0, av = 0;
#pragma unroll
    for (int j = 0; j < 4; j++) {
        int k = t * 4 + j;
        int l  = g_lowvalid[k];
        int a2 = (g_nc1[k] == 0.f) ? 1 : 0;
        lvloc[j] = l; avloc[j] = a2;
        lv += l; av += a2;
    }
    s_lv[t] = lv; s_av[t] = av;
    __syncthreads();
    for (int o = 1; o < 1024; o <<= 1) {
        int a = 0, b2 = 0;
        if (t >= o) { a = s_lv[t - o]; b2 = s_av[t - o]; }
        __syncthreads();
        if (t >= o) { s_lv[t] += a; s_av[t] += b2; }
        __syncthreads();
    }
    int nnew   = s_lv[1023];
    int navail = s_av[1023];
    int exlv = s_lv[t] - lv;
    int exav = s_av[t] - av;
#pragma unroll
    for (int j = 0; j < 4; j++) {
        int k = t * 4 + j;
        if (lvloc[j]) { g_validids[exlv] = k; exlv++; }
        if (avloc[j]) { g_availrank[k] = exav; exav++; }
    }
    if (t == 0) {
        g_nnew = nnew;
        g_ncreate = nnew < navail ? nnew : navail;
        out[0] = g_loss / (float)B_N;
    }
}

// ---------------- Kernel F: add_node slot fill ----------------
__global__ void addnode_kernel(float* __restrict__ out) {
    int k = blockIdx.x;
    if (g_nc1[k] != 0.f) return;
    int r = g_availrank[k];
    int ncreate = g_ncreate;
    if (r >= ncreate) return;
    int src = g_validids[g_nnew - ncreate + r];
    float inv = 1.f / g_cntl[src];

    float* outw   = out + 1;
    float* outma  = out + 1 + (size_t)K_N * D_N;
    float* outrel = out + 1 + 2 * (size_t)K_N * D_N;
    float* outnc  = out + 1 + 3 * (size_t)K_N * D_N;

    for (int d = threadIdx.x; d < D_N; d += blockDim.x) {
        size_t off = (size_t)k * D_N + d;
        outw[off]   = g_sumsl[(size_t)src * D_N + d] * inv;
        outma[off]  = 0.f;
        outrel[off] = 1.f;
    }
    if (threadIdx.x == 0) outnc[k] = 1.f;
}

// ---------------- launch ----------------
extern "C" void kernel_launch(void* const* d_in, const int* in_sizes, int n_in,
                              void* d_out, int out_size) {
    const float* X   = (const float*)d_in[0];
    const float* W   = (const float*)d_in[1];
    const float* MA  = (const float*)d_in[2];
    const float* REL = (const float*)d_in[3];
    const float* NC  = (const float*)d_in[4];
    float* out = (float*)d_out;

    void* p;
    cudaGetSymbolAddress(&p, g_cnt);   cudaMemsetAsync(p, 0, K_N * sizeof(float));
    cudaGetSymbolAddress(&p, g_cntl);  cudaMemsetAsync(p, 0, K_N * sizeof(float));
    cudaGetSymbolAddress(&p, g_sums);  cudaMemsetAsync(p, 0, (size_t)K_N * D_N * sizeof(float));
    cudaGetSymbolAddress(&p, g_sumsl); cudaMemsetAsync(p, 0, (size_t)K_N * D_N * sizeof(float));
    cudaGetSymbolAddress(&p, g_loss);  cudaMemsetAsync(p, 0, sizeof(float));

    split_stats_kernel<<<(B_N + K_N) / 8, 256>>>(X, W, REL);

    cudaFuncSetAttribute(gemm_mma_kernel, cudaFuncAttributeMaxDynamicSharedMemorySize, SMEM_TOTAL);
    dim3 grid(K_N / 128, B_N / 128);   // (32, 64) = 2048 CTAs
    gemm_mma_kernel<<<grid, NTHR, SMEM_TOTAL>>>();

    rescore_scatter_kernel<<<B_N / 8, 256>>>(X, W);
    update_kernel<<<K_N, 256>>>(W, MA, REL, NC, out);
    scan_kernel<<<1, 1024>>>(out);
    addnode_kernel<<<K_N, 256>>>(out);
}